// round 14
// baseline (speedup 1.0000x reference)
#include <cuda_runtime.h>

#define FULL 0xffffffffu
#define MAXNE 200000

__device__ float g_EW[MAXNE * 64];   // ent_emb @ W, precomputed per launch

__device__ __forceinline__ float sigmoidf_(float y) {
    return __fdividef(1.f, 1.f + __expf(-y));
}

// ---- packed f32x2 helpers (sm_103a FFMA2 path) ----
__device__ __forceinline__ unsigned long long pack2_(float a, float b) {
    unsigned long long r;
    asm("mov.b64 %0, {%1, %2};" : "=l"(r) : "f"(a), "f"(b));
    return r;
}
__device__ __forceinline__ void fma2_(unsigned long long& d,
                                      unsigned long long a, unsigned long long b) {
    asm("fma.rn.f32x2 %0, %1, %2, %0;" : "+l"(d) : "l"(a), "l"(b));
}
__device__ __forceinline__ void unpack2_(unsigned long long v, float& lo, float& hi) {
    asm("mov.b64 {%0, %1}, %2;" : "=f"(lo), "=f"(hi) : "l"(v));
}
__device__ __forceinline__ float sum2_(unsigned long long v) {
    float lo, hi; unpack2_(v, lo, hi);
    return lo + hi;
}

// ---------------- Kernel P: EW = ent_emb @ W (dense, FMA-bound) ----------------
// CTA tile: 128 rows x 64 cols, K=64. 256 threads = 16x16; thread owns 8 rows
// x 4 cols (2 packed col-pairs). A and W staged in smem; fma2 inner loop.
__global__ void __launch_bounds__(256, 4) ew_kernel(
    const float* __restrict__ E, const float* __restrict__ Wg, int NE)
{
    __shared__ float A[128][64];     // 32 KB
    __shared__ float Bs[64][64];     // 16 KB
    const int tid = threadIdx.x;
    const int ty = tid >> 4;         // 0..15 -> 8-row group
    const int tx = tid & 15;         // 0..15 -> 4-col group
    const int row0 = blockIdx.x * 128;

    // stage W (1024 float4)
    {
        const float4* w4 = (const float4*)Wg;
        float4* b4 = (float4*)Bs;
        #pragma unroll
        for (int i = 0; i < 4; i++) b4[tid + 256 * i] = w4[tid + 256 * i];
    }
    // stage A rows row0..row0+127 (2048 float4), guarded
    {
        float4* a4 = (float4*)A;
        const float4* e4 = (const float4*)E;
        #pragma unroll
        for (int i = 0; i < 8; i++) {
            int idx  = tid + 256 * i;          // float4 index in tile
            int grow = row0 + (idx >> 4);
            if (grow < NE) a4[idx] = e4[grow * 16 + (idx & 15)];
        }
    }
    __syncthreads();

    unsigned long long acc[8][2];
    #pragma unroll
    for (int i = 0; i < 8; i++) { acc[i][0] = 0ull; acc[i][1] = 0ull; }

    #pragma unroll 8
    for (int k = 0; k < 64; k++) {
        ulonglong2 bp = *(const ulonglong2*)&Bs[k][tx * 4];
        #pragma unroll
        for (int i = 0; i < 8; i++) {
            float a = A[ty * 8 + i][k];
            unsigned long long ap = pack2_(a, a);
            fma2_(acc[i][0], ap, bp.x);
            fma2_(acc[i][1], ap, bp.y);
        }
    }

    #pragma unroll
    for (int i = 0; i < 8; i++) {
        int grow = row0 + ty * 8 + i;
        if (grow < NE) {
            ulonglong2 o; o.x = acc[i][0]; o.y = acc[i][1];
            *(ulonglong2*)&g_EW[grow * 64 + tx * 4] = o;
        }
    }
}

// ---------------- Kernel F: gather/attention from EW + tiny iter-1 ----------------
// One CTA per FOUR batch elements, 256 threads. Phase C gathers from EW, so the
// aggregation output IS x@W: apply bias+sigmoid inline -> h directly. The whole
// iter-0 matvec phase (and its broadcast-LDS L1 traffic) is gone. Only iter-1's
// single 64-dot per element uses W.
__global__ void __launch_bounds__(256, 4) kgcn_kernel(
    const int* __restrict__ U, const int* __restrict__ V,
    const int* __restrict__ adj_ent, const int* __restrict__ adj_rel,
    const float* __restrict__ usr_emb, const float* __restrict__ rel_emb,
    const float* __restrict__ Wg, const float* __restrict__ bg,
    float* __restrict__ out, int NR)
{
    __shared__ float user_sh[4][64];
    __shared__ float urel_sh[4][32];
    __shared__ int   nbr_sh[4][272];   // [0..255] hop2 ents, [256..271] hop1 ents
    __shared__ int   rel_sh[4][272];
    __shared__ float attn16_sh[4][16];
    __shared__ int   v_sh[4];
    __shared__ __align__(16) float b_sh[64];
    __shared__ __align__(16) float h_sh[4][17][64];  // sigmoid outputs (h-space)
    __shared__ __align__(16) float x2_sh[4][64];
    __shared__ float red2_sh[4][4];

    const int tid   = threadIdx.x;
    const int col   = tid & 63;
    const int lane  = tid & 31;
    const int w     = tid >> 5;
    const int chunk = w & 3;          // 16-col chunk (final matvec)
    const int par   = w >> 2;
    const int halfL = lane >> 4;
    const int k15w  = lane & 15;
    const int mycol = chunk * 16 + k15w;

    const int b0 = 4 * blockIdx.x;
    int uu[4], vv[4];
    #pragma unroll
    for (int e = 0; e < 4; e++) { uu[e] = U[b0 + e]; vv[e] = V[b0 + e]; }

    // ---- Phase A: stage users, v, bias, hop-1 adjacency ----
    user_sh[tid >> 6][col] = usr_emb[uu[tid >> 6] * 64 + col];
    if (tid < 4) v_sh[tid] = vv[tid];
    if (tid >= 128 && tid < 192) b_sh[tid - 128] = bg[tid - 128];
    if (tid < 64) {
        int e = tid >> 4, j = tid & 15;
        nbr_sh[e][256 + j] = adj_ent[vv[e] * 16 + j];
        rel_sh[e][256 + j] = adj_rel[vv[e] * 16 + j];
    }
    __syncthreads();

    // ---- Phase B: hop-2 adjacency (4 elems) + urel tables ----
    {
        int j = tid & 15, pr = tid >> 4;
        #pragma unroll
        for (int e = 0; e < 4; e++) {
            int p = nbr_sh[e][256 + pr];
            nbr_sh[e][tid] = adj_ent[p * 16 + j];
            rel_sh[e][tid] = adj_rel[p * 16 + j];
        }
    }
    {
        int r = tid >> 3;
        int c = (tid & 7) * 8;
        float pa[4] = {0.f, 0.f, 0.f, 0.f};
        if (r < NR) {
            const float4* rp = (const float4*)(rel_emb + r * 64 + c);
            float4 aa = rp[0], bb = rp[1];
            #pragma unroll
            for (int e = 0; e < 4; e++)
                pa[e] = aa.x * user_sh[e][c+0] + aa.y * user_sh[e][c+1]
                      + aa.z * user_sh[e][c+2] + aa.w * user_sh[e][c+3]
                      + bb.x * user_sh[e][c+4] + bb.y * user_sh[e][c+5]
                      + bb.z * user_sh[e][c+6] + bb.w * user_sh[e][c+7];
        }
        #pragma unroll
        for (int o = 4; o > 0; o >>= 1) {
            #pragma unroll
            for (int e = 0; e < 4; e++)
                pa[e] += __shfl_down_sync(FULL, pa[e], o);
        }
        if ((tid & 7) == 0 && r < NR) {
            #pragma unroll
            for (int e = 0; e < 4; e++) urel_sh[e][r] = pa[e];
        }
    }
    __syncthreads();

    // ---- Phase C: softmax + aggregation IN W-SPACE (gather from EW),
    //      bias+sigmoid applied inline -> h_sh directly ----
    {
        const int hlf16 = lane & 16;
        const int k15   = lane & 15;
        const int hw    = 2 * w + halfL;      // half-warp id 0..15
        const int e     = hw & 3;
        const int rbase = hw >> 2;            // rows rbase, +4, +8, +12
        const ulonglong2* ewu2 = (const ulonglong2*)g_EW;
        const float4 bch = *(const float4*)&b_sh[k15 * 4];

        // self-initialized accumulators (loads issue before softmax chains)
        unsigned long long accA[4], accB[4];
        #pragma unroll
        for (int i = 0; i < 4; i++) {
            int r = rbase + 4 * i;
            ulonglong2 sv = ewu2[(nbr_sh[e][256 + r] << 4) + k15];
            accA[i] = sv.x; accB[i] = sv.y;
        }

        float sc[4], mx[4], ev[4], sm[4], pp[4];
        #pragma unroll
        for (int i = 0; i < 4; i++)
            sc[i] = urel_sh[e][rel_sh[e][((rbase + 4 * i) << 4) + k15]];
        #pragma unroll
        for (int i = 0; i < 4; i++) mx[i] = sc[i];
        #pragma unroll
        for (int o = 8; o > 0; o >>= 1) {
            #pragma unroll
            for (int i = 0; i < 4; i++)
                mx[i] = fmaxf(mx[i], __shfl_xor_sync(FULL, mx[i], o));
        }
        #pragma unroll
        for (int i = 0; i < 4; i++) { ev[i] = __expf(sc[i] - mx[i]); sm[i] = ev[i]; }
        #pragma unroll
        for (int o = 8; o > 0; o >>= 1) {
            #pragma unroll
            for (int i = 0; i < 4; i++)
                sm[i] += __shfl_xor_sync(FULL, sm[i], o);
        }
        #pragma unroll
        for (int i = 0; i < 4; i++) pp[i] = __fdividef(ev[i], sm[i]);

        const int* nb[4];
        #pragma unroll
        for (int i = 0; i < 4; i++) nb[i] = &nbr_sh[e][(rbase + 4 * i) << 4];
        #pragma unroll
        for (int k = 0; k < 16; k++) {
            #pragma unroll
            for (int i = 0; i < 4; i++) {
                float pk = __shfl_sync(FULL, pp[i], hlf16 + k);
                unsigned long long pkk = pack2_(pk, pk);
                ulonglong2 t = ewu2[(nb[i][k] << 4) + k15];
                fma2_(accA[i], pkk, t.x);
                fma2_(accB[i], pkk, t.y);
            }
        }
        // bias + sigmoid inline: acc IS xW
        #pragma unroll
        for (int i = 0; i < 4; i++) {
            float x0, x1, x2, x3;
            unpack2_(accA[i], x0, x1);
            unpack2_(accB[i], x2, x3);
            float h0v = sigmoidf_(x0 + bch.x);
            float h1v = sigmoidf_(x1 + bch.y);
            float h2v = sigmoidf_(x2 + bch.z);
            float h3v = sigmoidf_(x3 + bch.w);
            ulonglong2 o2; o2.x = pack2_(h0v, h1v); o2.y = pack2_(h2v, h3v);
            ((ulonglong2*)h_sh[e][rbase + 4 * i])[k15] = o2;
        }

        // hop-0 rows: half-warps 0..3 each take ONE hop-0 row
        if (hw < 4) {
            const int e2 = hw;
            unsigned long long a2A, a2B;
            {
                ulonglong2 sv2 = ewu2[(v_sh[e2] << 4) + k15];
                a2A = sv2.x; a2B = sv2.y;
            }
            float s2 = urel_sh[e2][rel_sh[e2][256 + k15]];
            float mx2 = s2;
            mx2 = fmaxf(mx2, __shfl_xor_sync(FULL, mx2, 8));
            mx2 = fmaxf(mx2, __shfl_xor_sync(FULL, mx2, 4));
            mx2 = fmaxf(mx2, __shfl_xor_sync(FULL, mx2, 2));
            mx2 = fmaxf(mx2, __shfl_xor_sync(FULL, mx2, 1));
            float ev2 = __expf(s2 - mx2);
            float sm2 = ev2;
            sm2 += __shfl_xor_sync(FULL, sm2, 8);
            sm2 += __shfl_xor_sync(FULL, sm2, 4);
            sm2 += __shfl_xor_sync(FULL, sm2, 2);
            sm2 += __shfl_xor_sync(FULL, sm2, 1);
            float p2 = __fdividef(ev2, sm2);
            attn16_sh[e2][k15] = p2;

            #pragma unroll
            for (int k = 0; k < 16; k++) {
                float pk = __shfl_sync(FULL, p2, hlf16 + k);
                unsigned long long pkk = pack2_(pk, pk);
                ulonglong2 t = ewu2[(nbr_sh[e2][256 + k] << 4) + k15];
                fma2_(a2A, pkk, t.x);
                fma2_(a2B, pkk, t.y);
            }
            float x0, x1, x2, x3;
            unpack2_(a2A, x0, x1);
            unpack2_(a2B, x2, x3);
            float h0v = sigmoidf_(x0 + bch.x);
            float h1v = sigmoidf_(x1 + bch.y);
            float h2v = sigmoidf_(x2 + bch.z);
            float h3v = sigmoidf_(x3 + bch.w);
            ulonglong2 o2; o2.x = pack2_(h0v, h1v); o2.y = pack2_(h2v, h3v);
            ((ulonglong2*)h_sh[e2][16])[k15] = o2;
        }
    }

    // ---- W half-column -> packed regs (only the final matvec needs W) ----
    unsigned long long Wp[16];
    #pragma unroll
    for (int i = 0; i < 16; i++) {
        float wa = Wg[(halfL * 32 + 2 * i) * 64 + mycol];
        float wb = Wg[(halfL * 32 + 2 * i + 1) * 64 + mycol];
        Wp[i] = pack2_(wa, wb);
    }
    const float bmy = bg[mycol];
    __syncthreads();

    // ---- Phase D: iter-1 agg (thread per (e,col)) ----
    {
        const int e = tid >> 6;
        float a0 = 0.f, a1 = 0.f, a2 = 0.f, a3 = 0.f;
        #pragma unroll
        for (int k = 0; k < 16; k += 4) {
            a0 = fmaf(attn16_sh[e][k + 0], h_sh[e][k + 0][col], a0);
            a1 = fmaf(attn16_sh[e][k + 1], h_sh[e][k + 1][col], a1);
            a2 = fmaf(attn16_sh[e][k + 2], h_sh[e][k + 2][col], a2);
            a3 = fmaf(attn16_sh[e][k + 3], h_sh[e][k + 3][col], a3);
        }
        x2_sh[e][col] = h_sh[e][16][col] + ((a0 + a1) + (a2 + a3));
    }
    __syncthreads();

    // ---- Final matvec + tanh + dot(user) — warp-autonomous, packed ----
    {
        for (int e = par; e < 4; e += 2) {
            unsigned long long Acc = 0ull;
            #pragma unroll
            for (int q = 0; q < 8; q++) {
                ulonglong2 v = *(const ulonglong2*)&x2_sh[e][halfL * 32 + 4*q];
                fma2_(Acc, v.x, Wp[2*q]);
                fma2_(Acc, v.y, Wp[2*q+1]);
            }
            float y = sum2_(Acc);
            float tot = y + __shfl_xor_sync(FULL, y, 16);
            float item = tanhf(tot + bmy);
            float t = user_sh[e][mycol] * item;   // lanes L, L+16 duplicate
            t += __shfl_xor_sync(FULL, t, 8);
            t += __shfl_xor_sync(FULL, t, 4);
            t += __shfl_xor_sync(FULL, t, 2);
            t += __shfl_xor_sync(FULL, t, 1);
            if (lane == 0) red2_sh[e][chunk] = t;
        }
    }
    __syncthreads();
    if (tid < 4)
        out[b0 + tid] = sigmoidf_((red2_sh[tid][0] + red2_sh[tid][1]) +
                                  (red2_sh[tid][2] + red2_sh[tid][3]));
}

extern "C" void kernel_launch(void* const* d_in, const int* in_sizes, int n_in,
                              void* d_out, int out_size) {
    const int*   U       = (const int*)d_in[0];
    const int*   V       = (const int*)d_in[1];
    const int*   adj_ent = (const int*)d_in[2];
    const int*   adj_rel = (const int*)d_in[3];
    const float* usr_emb = (const float*)d_in[4];
    const float* rel_emb = (const float*)d_in[5];
    const float* ent_emb = (const float*)d_in[6];
    const float* W       = (const float*)d_in[7];
    const float* bvec    = (const float*)d_in[8];
    float* out = (float*)d_out;

    const int B  = in_sizes[0];
    const int NR = in_sizes[5] / 64;
    const int NE = in_sizes[6] / 64;

    ew_kernel<<<(NE + 127) / 128, 256>>>(ent_emb, W, NE);
    kgcn_kernel<<<B / 4, 256>>>(U, V, adj_ent, adj_rel, usr_emb, rel_emb,
                                W, bvec, out, NR);
}

// round 15
// speedup vs baseline: 1.0181x; 1.0181x over previous
#include <cuda_runtime.h>

#define FULL 0xffffffffu
#define MAXNE 200000

__device__ float g_EW[MAXNE * 64];   // ent_emb @ W, precomputed per launch

__device__ __forceinline__ float sigmoidf_(float y) {
    return __fdividef(1.f, 1.f + __expf(-y));
}

// ---- packed f32x2 helpers (sm_103a FFMA2 path) ----
__device__ __forceinline__ unsigned long long pack2_(float a, float b) {
    unsigned long long r;
    asm("mov.b64 %0, {%1, %2};" : "=l"(r) : "f"(a), "f"(b));
    return r;
}
__device__ __forceinline__ void fma2_(unsigned long long& d,
                                      unsigned long long a, unsigned long long b) {
    asm("fma.rn.f32x2 %0, %1, %2, %0;" : "+l"(d) : "l"(a), "l"(b));
}
__device__ __forceinline__ void unpack2_(unsigned long long v, float& lo, float& hi) {
    asm("mov.b64 {%0, %1}, %2;" : "=f"(lo), "=f"(hi) : "l"(v));
}
__device__ __forceinline__ float sum2_(unsigned long long v) {
    float lo, hi; unpack2_(v, lo, hi);
    return lo + hi;
}

// ---------------- Kernel P: EW = ent_emb @ W (streamed row-matvec) ----------------
// 256 threads, occ 4. Warp owns 16 cols x k-half (Wp in 32 regs). 16-row chunks
// staged coalesced into a DOUBLE-BUFFERED smem; warp processes its 8 parity rows
// as pairs (rr, rr+8) with 2 accumulators. dot = 16 fma2 + shfl_xor(16).
__global__ void __launch_bounds__(256, 4) ew_kernel(
    const float* __restrict__ E, const float* __restrict__ Wg, int NE)
{
    __shared__ __align__(16) float xs[2][16][64];   // 8 KB double buffer

    const int tid   = threadIdx.x;
    const int lane  = tid & 31;
    const int w     = tid >> 5;
    const int chunk = w & 3;
    const int par   = w >> 2;
    const int halfL = lane >> 4;
    const int k15   = lane & 15;
    const int mycol = chunk * 16 + k15;

    unsigned long long Wp[16];
    #pragma unroll
    for (int i = 0; i < 16; i++) {
        float wa = Wg[(halfL * 32 + 2 * i) * 64 + mycol];
        float wb = Wg[(halfL * 32 + 2 * i + 1) * 64 + mycol];
        Wp[i] = pack2_(wa, wb);
    }

    const float4* E4 = (const float4*)E;   // 16 float4 per row
    const int nchunks = (NE + 15) >> 4;
    const int nf4 = NE * 16;
    const int stride = gridDim.x;

    // preload first chunk
    {
        int base = blockIdx.x * 256 + tid;
        if (base < nf4) ((float4*)xs[0])[tid] = E4[base];
    }
    __syncthreads();

    int buf = 0;
    for (int cc = blockIdx.x; cc < nchunks; cc += stride, buf ^= 1) {
        // prefetch next chunk into the other buffer
        int nxt = cc + stride;
        if (nxt < nchunks) {
            int base = nxt * 256 + tid;
            if (base < nf4) ((float4*)xs[buf ^ 1])[tid] = E4[base];
        }

        const int rowg0 = cc << 4;
        #pragma unroll
        for (int j = 0; j < 4; j++) {
            const int rr = par + 2 * j;          // rows rr and rr+8
            unsigned long long A0 = 0ull, A1 = 0ull;
            #pragma unroll
            for (int q = 0; q < 8; q++) {
                ulonglong2 v0 = *(const ulonglong2*)&xs[buf][rr][halfL * 32 + 4*q];
                ulonglong2 v1 = *(const ulonglong2*)&xs[buf][rr + 8][halfL * 32 + 4*q];
                fma2_(A0, v0.x, Wp[2*q]); fma2_(A0, v0.y, Wp[2*q+1]);
                fma2_(A1, v1.x, Wp[2*q]); fma2_(A1, v1.y, Wp[2*q+1]);
            }
            float y0 = sum2_(A0), y1 = sum2_(A1);
            float t0 = y0 + __shfl_xor_sync(FULL, y0, 16);
            float t1 = y1 + __shfl_xor_sync(FULL, y1, 16);
            if (halfL == 0) {
                int g0 = rowg0 + rr, g1 = rowg0 + rr + 8;
                if (g0 < NE) g_EW[g0 * 64 + mycol] = t0;
                if (g1 < NE) g_EW[g1 * 64 + mycol] = t1;
            }
        }
        __syncthreads();
    }
}

// ---------------- Kernel F: gather/attention from EW + tiny iter-1 ----------------
// (unchanged from R14: measured 66.5 us)
__global__ void __launch_bounds__(256, 4) kgcn_kernel(
    const int* __restrict__ U, const int* __restrict__ V,
    const int* __restrict__ adj_ent, const int* __restrict__ adj_rel,
    const float* __restrict__ usr_emb, const float* __restrict__ rel_emb,
    const float* __restrict__ Wg, const float* __restrict__ bg,
    float* __restrict__ out, int NR)
{
    __shared__ float user_sh[4][64];
    __shared__ float urel_sh[4][32];
    __shared__ int   nbr_sh[4][272];   // [0..255] hop2 ents, [256..271] hop1 ents
    __shared__ int   rel_sh[4][272];
    __shared__ float attn16_sh[4][16];
    __shared__ int   v_sh[4];
    __shared__ __align__(16) float b_sh[64];
    __shared__ __align__(16) float h_sh[4][17][64];  // sigmoid outputs (h-space)
    __shared__ __align__(16) float x2_sh[4][64];
    __shared__ float red2_sh[4][4];

    const int tid   = threadIdx.x;
    const int col   = tid & 63;
    const int lane  = tid & 31;
    const int w     = tid >> 5;
    const int chunk = w & 3;          // 16-col chunk (final matvec)
    const int par   = w >> 2;
    const int halfL = lane >> 4;
    const int k15w  = lane & 15;
    const int mycol = chunk * 16 + k15w;

    const int b0 = 4 * blockIdx.x;
    int uu[4], vv[4];
    #pragma unroll
    for (int e = 0; e < 4; e++) { uu[e] = U[b0 + e]; vv[e] = V[b0 + e]; }

    // ---- Phase A: stage users, v, bias, hop-1 adjacency ----
    user_sh[tid >> 6][col] = usr_emb[uu[tid >> 6] * 64 + col];
    if (tid < 4) v_sh[tid] = vv[tid];
    if (tid >= 128 && tid < 192) b_sh[tid - 128] = bg[tid - 128];
    if (tid < 64) {
        int e = tid >> 4, j = tid & 15;
        nbr_sh[e][256 + j] = adj_ent[vv[e] * 16 + j];
        rel_sh[e][256 + j] = adj_rel[vv[e] * 16 + j];
    }
    __syncthreads();

    // ---- Phase B: hop-2 adjacency (4 elems) + urel tables ----
    {
        int j = tid & 15, pr = tid >> 4;
        #pragma unroll
        for (int e = 0; e < 4; e++) {
            int p = nbr_sh[e][256 + pr];
            nbr_sh[e][tid] = adj_ent[p * 16 + j];
            rel_sh[e][tid] = adj_rel[p * 16 + j];
        }
    }
    {
        int r = tid >> 3;
        int c = (tid & 7) * 8;
        float pa[4] = {0.f, 0.f, 0.f, 0.f};
        if (r < NR) {
            const float4* rp = (const float4*)(rel_emb + r * 64 + c);
            float4 aa = rp[0], bb = rp[1];
            #pragma unroll
            for (int e = 0; e < 4; e++)
                pa[e] = aa.x * user_sh[e][c+0] + aa.y * user_sh[e][c+1]
                      + aa.z * user_sh[e][c+2] + aa.w * user_sh[e][c+3]
                      + bb.x * user_sh[e][c+4] + bb.y * user_sh[e][c+5]
                      + bb.z * user_sh[e][c+6] + bb.w * user_sh[e][c+7];
        }
        #pragma unroll
        for (int o = 4; o > 0; o >>= 1) {
            #pragma unroll
            for (int e = 0; e < 4; e++)
                pa[e] += __shfl_down_sync(FULL, pa[e], o);
        }
        if ((tid & 7) == 0 && r < NR) {
            #pragma unroll
            for (int e = 0; e < 4; e++) urel_sh[e][r] = pa[e];
        }
    }
    __syncthreads();

    // ---- Phase C: softmax + aggregation IN W-SPACE (gather from EW),
    //      bias+sigmoid applied inline -> h_sh directly ----
    {
        const int hlf16 = lane & 16;
        const int k15   = lane & 15;
        const int hw    = 2 * w + halfL;      // half-warp id 0..15
        const int e     = hw & 3;
        const int rbase = hw >> 2;            // rows rbase, +4, +8, +12
        const ulonglong2* ewu2 = (const ulonglong2*)g_EW;
        const float4 bch = *(const float4*)&b_sh[k15 * 4];

        // self-initialized accumulators (loads issue before softmax chains)
        unsigned long long accA[4], accB[4];
        #pragma unroll
        for (int i = 0; i < 4; i++) {
            int r = rbase + 4 * i;
            ulonglong2 sv = ewu2[(nbr_sh[e][256 + r] << 4) + k15];
            accA[i] = sv.x; accB[i] = sv.y;
        }

        float sc[4], mx[4], ev[4], sm[4], pp[4];
        #pragma unroll
        for (int i = 0; i < 4; i++)
            sc[i] = urel_sh[e][rel_sh[e][((rbase + 4 * i) << 4) + k15]];
        #pragma unroll
        for (int i = 0; i < 4; i++) mx[i] = sc[i];
        #pragma unroll
        for (int o = 8; o > 0; o >>= 1) {
            #pragma unroll
            for (int i = 0; i < 4; i++)
                mx[i] = fmaxf(mx[i], __shfl_xor_sync(FULL, mx[i], o));
        }
        #pragma unroll
        for (int i = 0; i < 4; i++) { ev[i] = __expf(sc[i] - mx[i]); sm[i] = ev[i]; }
        #pragma unroll
        for (int o = 8; o > 0; o >>= 1) {
            #pragma unroll
            for (int i = 0; i < 4; i++)
                sm[i] += __shfl_xor_sync(FULL, sm[i], o);
        }
        #pragma unroll
        for (int i = 0; i < 4; i++) pp[i] = __fdividef(ev[i], sm[i]);

        const int* nb[4];
        #pragma unroll
        for (int i = 0; i < 4; i++) nb[i] = &nbr_sh[e][(rbase + 4 * i) << 4];
        #pragma unroll
        for (int k = 0; k < 16; k++) {
            #pragma unroll
            for (int i = 0; i < 4; i++) {
                float pk = __shfl_sync(FULL, pp[i], hlf16 + k);
                unsigned long long pkk = pack2_(pk, pk);
                ulonglong2 t = ewu2[(nb[i][k] << 4) + k15];
                fma2_(accA[i], pkk, t.x);
                fma2_(accB[i], pkk, t.y);
            }
        }
        // bias + sigmoid inline: acc IS xW
        #pragma unroll
        for (int i = 0; i < 4; i++) {
            float x0, x1, x2, x3;
            unpack2_(accA[i], x0, x1);
            unpack2_(accB[i], x2, x3);
            float h0v = sigmoidf_(x0 + bch.x);
            float h1v = sigmoidf_(x1 + bch.y);
            float h2v = sigmoidf_(x2 + bch.z);
            float h3v = sigmoidf_(x3 + bch.w);
            ulonglong2 o2; o2.x = pack2_(h0v, h1v); o2.y = pack2_(h2v, h3v);
            ((ulonglong2*)h_sh[e][rbase + 4 * i])[k15] = o2;
        }

        // hop-0 rows: half-warps 0..3 each take ONE hop-0 row
        if (hw < 4) {
            const int e2 = hw;
            unsigned long long a2A, a2B;
            {
                ulonglong2 sv2 = ewu2[(v_sh[e2] << 4) + k15];
                a2A = sv2.x; a2B = sv2.y;
            }
            float s2 = urel_sh[e2][rel_sh[e2][256 + k15]];
            float mx2 = s2;
            mx2 = fmaxf(mx2, __shfl_xor_sync(FULL, mx2, 8));
            mx2 = fmaxf(mx2, __shfl_xor_sync(FULL, mx2, 4));
            mx2 = fmaxf(mx2, __shfl_xor_sync(FULL, mx2, 2));
            mx2 = fmaxf(mx2, __shfl_xor_sync(FULL, mx2, 1));
            float ev2 = __expf(s2 - mx2);
            float sm2 = ev2;
            sm2 += __shfl_xor_sync(FULL, sm2, 8);
            sm2 += __shfl_xor_sync(FULL, sm2, 4);
            sm2 += __shfl_xor_sync(FULL, sm2, 2);
            sm2 += __shfl_xor_sync(FULL, sm2, 1);
            float p2 = __fdividef(ev2, sm2);
            attn16_sh[e2][k15] = p2;

            #pragma unroll
            for (int k = 0; k < 16; k++) {
                float pk = __shfl_sync(FULL, p2, hlf16 + k);
                unsigned long long pkk = pack2_(pk, pk);
                ulonglong2 t = ewu2[(nbr_sh[e2][256 + k] << 4) + k15];
                fma2_(a2A, pkk, t.x);
                fma2_(a2B, pkk, t.y);
            }
            float x0, x1, x2, x3;
            unpack2_(a2A, x0, x1);
            unpack2_(a2B, x2, x3);
            float h0v = sigmoidf_(x0 + bch.x);
            float h1v = sigmoidf_(x1 + bch.y);
            float h2v = sigmoidf_(x2 + bch.z);
            float h3v = sigmoidf_(x3 + bch.w);
            ulonglong2 o2; o2.x = pack2_(h0v, h1v); o2.y = pack2_(h2v, h3v);
            ((ulonglong2*)h_sh[e2][16])[k15] = o2;
        }
    }

    // ---- W half-column -> packed regs (only the final matvec needs W) ----
    unsigned long long Wp[16];
    #pragma unroll
    for (int i = 0; i < 16; i++) {
        float wa = Wg[(halfL * 32 + 2 * i) * 64 + mycol];
        float wb = Wg[(halfL * 32 + 2 * i + 1) * 64 + mycol];
        Wp[i] = pack2_(wa, wb);
    }
    const float bmy = bg[mycol];
    __syncthreads();

    // ---- Phase D: iter-1 agg (thread per (e,col)) ----
    {
        const int e = tid >> 6;
        float a0 = 0.f, a1 = 0.f, a2 = 0.f, a3 = 0.f;
        #pragma unroll
        for (int k = 0; k < 16; k += 4) {
            a0 = fmaf(attn16_sh[e][k + 0], h_sh[e][k + 0][col], a0);
            a1 = fmaf(attn16_sh[e][k + 1], h_sh[e][k + 1][col], a1);
            a2 = fmaf(attn16_sh[e][k + 2], h_sh[e][k + 2][col], a2);
            a3 = fmaf(attn16_sh[e][k + 3], h_sh[e][k + 3][col], a3);
        }
        x2_sh[e][col] = h_sh[e][16][col] + ((a0 + a1) + (a2 + a3));
    }
    __syncthreads();

    // ---- Final matvec + tanh + dot(user) — warp-autonomous, packed ----
    {
        for (int e = par; e < 4; e += 2) {
            unsigned long long Acc = 0ull;
            #pragma unroll
            for (int q = 0; q < 8; q++) {
                ulonglong2 v = *(const ulonglong2*)&x2_sh[e][halfL * 32 + 4*q];
                fma2_(Acc, v.x, Wp[2*q]);
                fma2_(Acc, v.y, Wp[2*q+1]);
            }
            float y = sum2_(Acc);
            float tot = y + __shfl_xor_sync(FULL, y, 16);
            float item = tanhf(tot + bmy);
            float t = user_sh[e][mycol] * item;   // lanes L, L+16 duplicate
            t += __shfl_xor_sync(FULL, t, 8);
            t += __shfl_xor_sync(FULL, t, 4);
            t += __shfl_xor_sync(FULL, t, 2);
            t += __shfl_xor_sync(FULL, t, 1);
            if (lane == 0) red2_sh[e][chunk] = t;
        }
    }
    __syncthreads();
    if (tid < 4)
        out[b0 + tid] = sigmoidf_((red2_sh[tid][0] + red2_sh[tid][1]) +
                                  (red2_sh[tid][2] + red2_sh[tid][3]));
}

extern "C" void kernel_launch(void* const* d_in, const int* in_sizes, int n_in,
                              void* d_out, int out_size) {
    const int*   U       = (const int*)d_in[0];
    const int*   V       = (const int*)d_in[1];
    const int*   adj_ent = (const int*)d_in[2];
    const int*   adj_rel = (const int*)d_in[3];
    const float* usr_emb = (const float*)d_in[4];
    const float* rel_emb = (const float*)d_in[5];
    const float* ent_emb = (const float*)d_in[6];
    const float* W       = (const float*)d_in[7];
    const float* bvec    = (const float*)d_in[8];
    float* out = (float*)d_out;

    const int B  = in_sizes[0];
    const int NR = in_sizes[5] / 64;
    const int NE = in_sizes[6] / 64;

    ew_kernel<<<2048, 256>>>(ent_emb, W, NE);
    kgcn_kernel<<<B / 4, 256>>>(U, V, adj_ent, adj_rel, usr_emb, rel_emb,
                                W, bvec, out, NR);
}

// round 16
// speedup vs baseline: 1.4154x; 1.3902x over previous
#include <cuda_runtime.h>

#define FULL 0xffffffffu
#define MAXNE 200000

__device__ float g_EW[MAXNE * 64];   // ent_emb @ W, precomputed per launch

__device__ __forceinline__ float sigmoidf_(float y) {
    return __fdividef(1.f, 1.f + __expf(-y));
}

// ---- packed f32x2 helpers (sm_103a FFMA2 path) ----
__device__ __forceinline__ unsigned long long pack2_(float a, float b) {
    unsigned long long r;
    asm("mov.b64 %0, {%1, %2};" : "=l"(r) : "f"(a), "f"(b));
    return r;
}
__device__ __forceinline__ void fma2_(unsigned long long& d,
                                      unsigned long long a, unsigned long long b) {
    asm("fma.rn.f32x2 %0, %1, %2, %0;" : "+l"(d) : "l"(a), "l"(b));
}
__device__ __forceinline__ void unpack2_(unsigned long long v, float& lo, float& hi) {
    asm("mov.b64 {%0, %1}, %2;" : "=f"(lo), "=f"(hi) : "l"(v));
}
__device__ __forceinline__ float sum2_(unsigned long long v) {
    float lo, hi; unpack2_(v, lo, hi);
    return lo + hi;
}
__device__ __forceinline__ unsigned tf32_(float f) {
    unsigned r;
    asm("cvt.rna.tf32.f32 %0, %1;" : "=r"(r) : "f"(f));
    return r;
}

// ---------------- Kernel P: EW = ent_emb @ W on TENSOR CORES ----------------
// mma.sync.m16n8k8.tf32. CTA = 256 thr = 8 warps = 2 row-halves x 4 col-quarters.
// Per 32-row block: stage E (double-buffered, 68-float padded rows -> conflict-
// free A-fragment LDS), W fragments held in 32 regs per warp (built once).
__global__ void __launch_bounds__(256, 4) ew_tc_kernel(
    const float* __restrict__ E, const float* __restrict__ Wg, int NE)
{
    __shared__ __align__(16) float es[2][32][68];   // padded: bank = 4g+tg, conflict-free

    const int tid  = threadIdx.x;
    const int lane = tid & 31;
    const int w    = tid >> 5;
    const int rb   = w >> 2;        // row half of the 32-row block (0/1)
    const int nb   = w & 3;         // 16-col quarter
    const int g    = lane >> 2;     // groupID 0..7
    const int tg   = lane & 3;      // thread-in-group 0..3

    // B fragments (W is the same for every block): 2 n-tiles x 8 k-steps x 2 regs
    unsigned bfr[2][8][2];
    #pragma unroll
    for (int nt = 0; nt < 2; nt++) {
        #pragma unroll
        for (int kk = 0; kk < 8; kk++) {
            int ncol = nb * 16 + nt * 8 + g;
            bfr[nt][kk][0] = tf32_(Wg[(kk * 8 + tg) * 64 + ncol]);
            bfr[nt][kk][1] = tf32_(Wg[(kk * 8 + tg + 4) * 64 + ncol]);
        }
    }

    const float4* E4 = (const float4*)E;
    const int nblocks = (NE + 31) >> 5;
    const int nf4 = NE * 16;
    const int stride = gridDim.x;

    // preload first block (2 float4 per thread; row = idx>>4, col4 = idx&15)
    {
        int blk = blockIdx.x;
        if (blk < nblocks) {
            #pragma unroll
            for (int i = 0; i < 2; i++) {
                int idx = tid + 256 * i;
                int gi = blk * 512 + idx;
                if (gi < nf4)
                    *(float4*)&es[0][idx >> 4][(idx & 15) * 4] = E4[gi];
            }
        }
    }
    __syncthreads();

    int buf = 0;
    for (int blk = blockIdx.x; blk < nblocks; blk += stride, buf ^= 1) {
        // prefetch next block into the other buffer
        int nxt = blk + stride;
        if (nxt < nblocks) {
            #pragma unroll
            for (int i = 0; i < 2; i++) {
                int idx = tid + 256 * i;
                int gi = nxt * 512 + idx;
                if (gi < nf4)
                    *(float4*)&es[buf ^ 1][idx >> 4][(idx & 15) * 4] = E4[gi];
            }
        }

        float c0[4] = {0.f, 0.f, 0.f, 0.f};
        float c1[4] = {0.f, 0.f, 0.f, 0.f};
        #pragma unroll
        for (int kk = 0; kk < 8; kk++) {
            unsigned a0 = tf32_(es[buf][rb * 16 + g][kk * 8 + tg]);
            unsigned a1 = tf32_(es[buf][rb * 16 + g + 8][kk * 8 + tg]);
            unsigned a2 = tf32_(es[buf][rb * 16 + g][kk * 8 + tg + 4]);
            unsigned a3 = tf32_(es[buf][rb * 16 + g + 8][kk * 8 + tg + 4]);
            asm volatile(
                "mma.sync.aligned.m16n8k8.row.col.f32.tf32.tf32.f32 "
                "{%0,%1,%2,%3}, {%4,%5,%6,%7}, {%8,%9}, {%0,%1,%2,%3};"
                : "+f"(c0[0]), "+f"(c0[1]), "+f"(c0[2]), "+f"(c0[3])
                : "r"(a0), "r"(a1), "r"(a2), "r"(a3),
                  "r"(bfr[0][kk][0]), "r"(bfr[0][kk][1]));
            asm volatile(
                "mma.sync.aligned.m16n8k8.row.col.f32.tf32.tf32.f32 "
                "{%0,%1,%2,%3}, {%4,%5,%6,%7}, {%8,%9}, {%0,%1,%2,%3};"
                : "+f"(c1[0]), "+f"(c1[1]), "+f"(c1[2]), "+f"(c1[3])
                : "r"(a0), "r"(a1), "r"(a2), "r"(a3),
                  "r"(bfr[1][kk][0]), "r"(bfr[1][kk][1]));
        }

        // store: D rows (g, g+8), cols nb*16 + nt*8 + 2tg (+1) -> STG.64
        {
            int r0 = blk * 32 + rb * 16 + g;
            int r1 = r0 + 8;
            int cbase = nb * 16 + 2 * tg;
            if (r0 < NE) {
                *(unsigned long long*)&g_EW[r0 * 64 + cbase]     = pack2_(c0[0], c0[1]);
                *(unsigned long long*)&g_EW[r0 * 64 + cbase + 8] = pack2_(c1[0], c1[1]);
            }
            if (r1 < NE) {
                *(unsigned long long*)&g_EW[r1 * 64 + cbase]     = pack2_(c0[2], c0[3]);
                *(unsigned long long*)&g_EW[r1 * 64 + cbase + 8] = pack2_(c1[2], c1[3]);
            }
        }
        __syncthreads();
    }
}

// ---------------- Kernel F: gather/attention from EW + tiny iter-1 ----------------
// (unchanged: measured 67.8 us)
__global__ void __launch_bounds__(256, 4) kgcn_kernel(
    const int* __restrict__ U, const int* __restrict__ V,
    const int* __restrict__ adj_ent, const int* __restrict__ adj_rel,
    const float* __restrict__ usr_emb, const float* __restrict__ rel_emb,
    const float* __restrict__ Wg, const float* __restrict__ bg,
    float* __restrict__ out, int NR)
{
    __shared__ float user_sh[4][64];
    __shared__ float urel_sh[4][32];
    __shared__ int   nbr_sh[4][272];   // [0..255] hop2 ents, [256..271] hop1 ents
    __shared__ int   rel_sh[4][272];
    __shared__ float attn16_sh[4][16];
    __shared__ int   v_sh[4];
    __shared__ __align__(16) float b_sh[64];
    __shared__ __align__(16) float h_sh[4][17][64];  // sigmoid outputs (h-space)
    __shared__ __align__(16) float x2_sh[4][64];
    __shared__ float red2_sh[4][4];

    const int tid   = threadIdx.x;
    const int col   = tid & 63;
    const int lane  = tid & 31;
    const int w     = tid >> 5;
    const int chunk = w & 3;          // 16-col chunk (final matvec)
    const int par   = w >> 2;
    const int halfL = lane >> 4;
    const int k15w  = lane & 15;
    const int mycol = chunk * 16 + k15w;

    const int b0 = 4 * blockIdx.x;
    int uu[4], vv[4];
    #pragma unroll
    for (int e = 0; e < 4; e++) { uu[e] = U[b0 + e]; vv[e] = V[b0 + e]; }

    // ---- Phase A: stage users, v, bias, hop-1 adjacency ----
    user_sh[tid >> 6][col] = usr_emb[uu[tid >> 6] * 64 + col];
    if (tid < 4) v_sh[tid] = vv[tid];
    if (tid >= 128 && tid < 192) b_sh[tid - 128] = bg[tid - 128];
    if (tid < 64) {
        int e = tid >> 4, j = tid & 15;
        nbr_sh[e][256 + j] = adj_ent[vv[e] * 16 + j];
        rel_sh[e][256 + j] = adj_rel[vv[e] * 16 + j];
    }
    __syncthreads();

    // ---- Phase B: hop-2 adjacency (4 elems) + urel tables ----
    {
        int j = tid & 15, pr = tid >> 4;
        #pragma unroll
        for (int e = 0; e < 4; e++) {
            int p = nbr_sh[e][256 + pr];
            nbr_sh[e][tid] = adj_ent[p * 16 + j];
            rel_sh[e][tid] = adj_rel[p * 16 + j];
        }
    }
    {
        int r = tid >> 3;
        int c = (tid & 7) * 8;
        float pa[4] = {0.f, 0.f, 0.f, 0.f};
        if (r < NR) {
            const float4* rp = (const float4*)(rel_emb + r * 64 + c);
            float4 aa = rp[0], bb = rp[1];
            #pragma unroll
            for (int e = 0; e < 4; e++)
                pa[e] = aa.x * user_sh[e][c+0] + aa.y * user_sh[e][c+1]
                      + aa.z * user_sh[e][c+2] + aa.w * user_sh[e][c+3]
                      + bb.x * user_sh[e][c+4] + bb.y * user_sh[e][c+5]
                      + bb.z * user_sh[e][c+6] + bb.w * user_sh[e][c+7];
        }
        #pragma unroll
        for (int o = 4; o > 0; o >>= 1) {
            #pragma unroll
            for (int e = 0; e < 4; e++)
                pa[e] += __shfl_down_sync(FULL, pa[e], o);
        }
        if ((tid & 7) == 0 && r < NR) {
            #pragma unroll
            for (int e = 0; e < 4; e++) urel_sh[e][r] = pa[e];
        }
    }
    __syncthreads();

    // ---- Phase C: softmax + aggregation IN W-SPACE (gather from EW),
    //      bias+sigmoid applied inline -> h_sh directly ----
    {
        const int hlf16 = lane & 16;
        const int k15   = lane & 15;
        const int hw    = 2 * w + halfL;      // half-warp id 0..15
        const int e     = hw & 3;
        const int rbase = hw >> 2;            // rows rbase, +4, +8, +12
        const ulonglong2* ewu2 = (const ulonglong2*)g_EW;
        const float4 bch = *(const float4*)&b_sh[k15 * 4];

        // self-initialized accumulators (loads issue before softmax chains)
        unsigned long long accA[4], accB[4];
        #pragma unroll
        for (int i = 0; i < 4; i++) {
            int r = rbase + 4 * i;
            ulonglong2 sv = ewu2[(nbr_sh[e][256 + r] << 4) + k15];
            accA[i] = sv.x; accB[i] = sv.y;
        }

        float sc[4], mx[4], ev[4], sm[4], pp[4];
        #pragma unroll
        for (int i = 0; i < 4; i++)
            sc[i] = urel_sh[e][rel_sh[e][((rbase + 4 * i) << 4) + k15]];
        #pragma unroll
        for (int i = 0; i < 4; i++) mx[i] = sc[i];
        #pragma unroll
        for (int o = 8; o > 0; o >>= 1) {
            #pragma unroll
            for (int i = 0; i < 4; i++)
                mx[i] = fmaxf(mx[i], __shfl_xor_sync(FULL, mx[i], o));
        }
        #pragma unroll
        for (int i = 0; i < 4; i++) { ev[i] = __expf(sc[i] - mx[i]); sm[i] = ev[i]; }
        #pragma unroll
        for (int o = 8; o > 0; o >>= 1) {
            #pragma unroll
            for (int i = 0; i < 4; i++)
                sm[i] += __shfl_xor_sync(FULL, sm[i], o);
        }
        #pragma unroll
        for (int i = 0; i < 4; i++) pp[i] = __fdividef(ev[i], sm[i]);

        const int* nb[4];
        #pragma unroll
        for (int i = 0; i < 4; i++) nb[i] = &nbr_sh[e][(rbase + 4 * i) << 4];
        #pragma unroll
        for (int k = 0; k < 16; k++) {
            #pragma unroll
            for (int i = 0; i < 4; i++) {
                float pk = __shfl_sync(FULL, pp[i], hlf16 + k);
                unsigned long long pkk = pack2_(pk, pk);
                ulonglong2 t = ewu2[(nb[i][k] << 4) + k15];
                fma2_(accA[i], pkk, t.x);
                fma2_(accB[i], pkk, t.y);
            }
        }
        // bias + sigmoid inline: acc IS xW
        #pragma unroll
        for (int i = 0; i < 4; i++) {
            float x0, x1, x2, x3;
            unpack2_(accA[i], x0, x1);
            unpack2_(accB[i], x2, x3);
            float h0v = sigmoidf_(x0 + bch.x);
            float h1v = sigmoidf_(x1 + bch.y);
            float h2v = sigmoidf_(x2 + bch.z);
            float h3v = sigmoidf_(x3 + bch.w);
            ulonglong2 o2; o2.x = pack2_(h0v, h1v); o2.y = pack2_(h2v, h3v);
            ((ulonglong2*)h_sh[e][rbase + 4 * i])[k15] = o2;
        }

        // hop-0 rows: half-warps 0..3 each take ONE hop-0 row
        if (hw < 4) {
            const int e2 = hw;
            unsigned long long a2A, a2B;
            {
                ulonglong2 sv2 = ewu2[(v_sh[e2] << 4) + k15];
                a2A = sv2.x; a2B = sv2.y;
            }
            float s2 = urel_sh[e2][rel_sh[e2][256 + k15]];
            float mx2 = s2;
            mx2 = fmaxf(mx2, __shfl_xor_sync(FULL, mx2, 8));
            mx2 = fmaxf(mx2, __shfl_xor_sync(FULL, mx2, 4));
            mx2 = fmaxf(mx2, __shfl_xor_sync(FULL, mx2, 2));
            mx2 = fmaxf(mx2, __shfl_xor_sync(FULL, mx2, 1));
            float ev2 = __expf(s2 - mx2);
            float sm2 = ev2;
            sm2 += __shfl_xor_sync(FULL, sm2, 8);
            sm2 += __shfl_xor_sync(FULL, sm2, 4);
            sm2 += __shfl_xor_sync(FULL, sm2, 2);
            sm2 += __shfl_xor_sync(FULL, sm2, 1);
            float p2 = __fdividef(ev2, sm2);
            attn16_sh[e2][k15] = p2;

            #pragma unroll
            for (int k = 0; k < 16; k++) {
                float pk = __shfl_sync(FULL, p2, hlf16 + k);
                unsigned long long pkk = pack2_(pk, pk);
                ulonglong2 t = ewu2[(nbr_sh[e2][256 + k] << 4) + k15];
                fma2_(a2A, pkk, t.x);
                fma2_(a2B, pkk, t.y);
            }
            float x0, x1, x2, x3;
            unpack2_(a2A, x0, x1);
            unpack2_(a2B, x2, x3);
            float h0v = sigmoidf_(x0 + bch.x);
            float h1v = sigmoidf_(x1 + bch.y);
            float h2v = sigmoidf_(x2 + bch.z);
            float h3v = sigmoidf_(x3 + bch.w);
            ulonglong2 o2; o2.x = pack2_(h0v, h1v); o2.y = pack2_(h2v, h3v);
            ((ulonglong2*)h_sh[e2][16])[k15] = o2;
        }
    }

    // ---- W half-column -> packed regs (only the final matvec needs W) ----
    unsigned long long Wp[16];
    #pragma unroll
    for (int i = 0; i < 16; i++) {
        float wa = Wg[(halfL * 32 + 2 * i) * 64 + mycol];
        float wb = Wg[(halfL * 32 + 2 * i + 1) * 64 + mycol];
        Wp[i] = pack2_(wa, wb);
    }
    const float bmy = bg[mycol];
    __syncthreads();

    // ---- Phase D: iter-1 agg (thread per (e,col)) ----
    {
        const int e = tid >> 6;
        float a0 = 0.f, a1 = 0.f, a2 = 0.f, a3 = 0.f;
        #pragma unroll
        for (int k = 0; k < 16; k += 4) {
            a0 = fmaf(attn16_sh[e][k + 0], h_sh[e][k + 0][col], a0);
            a1 = fmaf(attn16_sh[e][k + 1], h_sh[e][k + 1][col], a1);
            a2 = fmaf(attn16_sh[e][k + 2], h_sh[e][k + 2][col], a2);
            a3 = fmaf(attn16_sh[e][k + 3], h_sh[e][k + 3][col], a3);
        }
        x2_sh[e][col] = h_sh[e][16][col] + ((a0 + a1) + (a2 + a3));
    }
    __syncthreads();

    // ---- Final matvec + tanh + dot(user) — warp-autonomous, packed ----
    {
        for (int e = par; e < 4; e += 2) {
            unsigned long long Acc = 0ull;
            #pragma unroll
            for (int q = 0; q < 8; q++) {
                ulonglong2 v = *(const ulonglong2*)&x2_sh[e][halfL * 32 + 4*q];
                fma2_(Acc, v.x, Wp[2*q]);
                fma2_(Acc, v.y, Wp[2*q+1]);
            }
            float y = sum2_(Acc);
            float tot = y + __shfl_xor_sync(FULL, y, 16);
            float item = tanhf(tot + bmy);
            float t = user_sh[e][mycol] * item;   // lanes L, L+16 duplicate
            t += __shfl_xor_sync(FULL, t, 8);
            t += __shfl_xor_sync(FULL, t, 4);
            t += __shfl_xor_sync(FULL, t, 2);
            t += __shfl_xor_sync(FULL, t, 1);
            if (lane == 0) red2_sh[e][chunk] = t;
        }
    }
    __syncthreads();
    if (tid < 4)
        out[b0 + tid] = sigmoidf_((red2_sh[tid][0] + red2_sh[tid][1]) +
                                  (red2_sh[tid][2] + red2_sh[tid][3]));
}

extern "C" void kernel_launch(void* const* d_in, const int* in_sizes, int n_in,
                              void* d_out, int out_size) {
    const int*   U       = (const int*)d_in[0];
    const int*   V       = (const int*)d_in[1];
    const int*   adj_ent = (const int*)d_in[2];
    const int*   adj_rel = (const int*)d_in[3];
    const float* usr_emb = (const float*)d_in[4];
    const float* rel_emb = (const float*)d_in[5];
    const float* ent_emb = (const float*)d_in[6];
    const float* W       = (const float*)d_in[7];
    const float* bvec    = (const float*)d_in[8];
    float* out = (float*)d_out;

    const int B  = in_sizes[0];
    const int NR = in_sizes[5] / 64;
    const int NE = in_sizes[6] / 64;

    ew_tc_kernel<<<1024, 256>>>(ent_emb, W, NE);
    kgcn_kernel<<<B / 4, 256>>>(U, V, adj_ent, adj_rel, usr_emb, rel_emb,
                                W, bvec, out, NR);
}